// round 13
// baseline (speedup 1.0000x reference)
#include <cuda_runtime.h>

// WOS 3x3 filter — float-key sorting network, PIPE-PROBE variant.
//
// Identical to the 49.3us R12 kernel except: compare-exchanges in the p>=16
// Batcher pass groups are expressed as setp.gt.f32 + 2x selp.f32 (inline asm)
// instead of fmaxf/fminf. If FSEL executes on the fma pipe (undocumented),
// ~55% of the network moves off the saturated alu pipe (74% busy) onto the
// idle fma pipe (8.5% busy). Bit-exact either way: selp returns original
// operands; key ordering semantics unchanged.

#define NCH 16
#define DD 54
#define HH 64
#define WW 64
#define PIX_PER_BLK 8
#define NTHREADS 128
#define TILE_COLS (PIX_PER_BLK + 2)    // 10
#define TILE_ELEMS (3 * 3 * TILE_COLS) // 90
#define WSTRIDE 65
#define ZTOL 1e-6f

__global__ __launch_bounds__(NTHREADS, 7)
void wos_kernel(const float* __restrict__ x,
                const float* __restrict__ mask,
                const float* __restrict__ weight,
                const float* __restrict__ bias,
                float* __restrict__ out)
{
    __shared__ float  tile_s[TILE_ELEMS];
    __shared__ float2 mp_s[NCH * 27];       // (mask[d0], mask[27+d0]) pairs
    __shared__ float  w2_s[NCH * WSTRIDE];  // slot-indexed weights
    __shared__ float  bias_s[NCH];
    __shared__ int    toff_s[DD];
    __shared__ int    tiny_s;

    const int tid = threadIdx.x;
    const int c  = tid & (NCH - 1);
    const int ty = tid >> 4;

    const int pix0 = blockIdx.x * PIX_PER_BLK;
    const int b    = pix0 >> 12;
    const int rem  = pix0 & 4095;
    const int h    = rem >> 6;
    const int w0   = rem & 63;

    if (tid == 0) tiny_s = 0;

    // ---- cooperative staging ----
    float* mflat_all = (float*)mp_s;
    #pragma unroll
    for (int idx = tid; idx < NCH * DD; idx += NTHREADS) {
        const int cw = idx / DD;
        const int d  = idx - cw * DD;
        const float wgt = weight[idx];
        const int dst = cw * DD + ((d < 27) ? (2 * d) : (2 * d - 53));
        mflat_all[dst] = mask[idx];
        w2_s[cw * WSTRIDE + (53 - d)] = wgt;   // slot 63-d stored at slot-10
        if (wgt <= ZTOL) tiny_s = 1;
    }
    if (tid < NCH) bias_s[tid] = bias[tid];
    if (tid < DD) {
        const int d0 = (tid < 27) ? tid : tid - 27;
        toff_s[tid] = ((d0 / 9) * 3 + ((d0 / 3) % 3)) * TILE_COLS + (d0 % 3);
    }
    #pragma unroll
    for (int idx = tid; idx < TILE_ELEMS; idx += NTHREADS) {
        int cc  = idx / (3 * TILE_COLS);
        int r   = (idx / TILE_COLS) % 3;
        int col = idx % TILE_COLS;
        int gh = h + r - 1;
        int gw = w0 + col - 1;
        float v = 0.0f;
        if (gh >= 0 && gh < HH && gw >= 0 && gw < WW)
            v = x[((b * 3 + cc) * HH + gh) * WW + gw];
        tile_s[idx] = v;
    }
    __syncthreads();

    const float*  wrow  = &w2_s[c * WSTRIDE] - 10;
    const float2* mprow = &mp_s[c * 27];
    const float*  mflat = (const float*)mprow;
    const bool    tinyw = (tiny_s != 0);
    const float   bs = bias_s[c];

    // ---- build float keys (regs only) ----
    float key[DD];
    #pragma unroll
    for (int d0 = 0; d0 < 27; d0++) {
        const int cc = d0 / 9;
        const int r  = (d0 / 3) % 3;
        const int j  = d0 % 3;
        const float2 mm = mprow[d0];
        float t  = tile_s[(cc * 3 + r) * TILE_COLS + ty + j];
        float fp = t + mm.x;                // element d0    -> slot 63-d0
        float fm = mm.y - t;                // element 27+d0 -> slot 36-d0
        unsigned up = __float_as_uint(fp);
        unsigned um = __float_as_uint(fm);
        key[d0]      = __uint_as_float((up | 63u) ^ (unsigned)(63 ^ (63 - d0)));
        key[27 + d0] = __uint_as_float((um | 63u) ^ (unsigned)(63 ^ (36 - d0)));
    }

    // ---- Batcher odd-even merge sort, descending, n=54 ----
    // CE  : FMNMX pair (alu pipe)
    // CE_S: setp.gt + 2x selp (probe: possibly fma pipe)
#define CE(A, B)                                 \
    do {                                         \
        float ka = key[A], kb = key[B];          \
        key[A] = fmaxf(ka, kb);                  \
        key[B] = fminf(ka, kb);                  \
    } while (0)

#define CE_S(A, B)                                                   \
    do {                                                             \
        float ka = key[A], kb = key[B];                              \
        float mx, mn;                                                \
        asm("{\n\t"                                                  \
            ".reg .pred p;\n\t"                                      \
            "setp.gt.f32 p, %2, %3;\n\t"                             \
            "selp.f32 %0, %2, %3, p;\n\t"                            \
            "selp.f32 %1, %3, %2, p;\n\t"                            \
            "}"                                                      \
            : "=f"(mx), "=f"(mn) : "f"(ka), "f"(kb));                \
        key[A] = mx;                                                 \
        key[B] = mn;                                                 \
    } while (0)

#define PASS_G(CEOP, P, K)                                                  \
    _Pragma("unroll")                                                       \
    for (int j = (K) % (P); j + (K) < DD; j += 2 * (K)) {                   \
        _Pragma("unroll")                                                   \
        for (int i = 0; i < (K); i++) {                                     \
            const int a  = i + j;                                           \
            const int bb = i + j + (K);                                     \
            if (bb < DD && (a / (2 * (P))) == (bb / (2 * (P))))             \
                CEOP(a, bb);                                                \
        }                                                                   \
    }

    PASS_G(CE, 1, 1)
    PASS_G(CE, 2, 2)  PASS_G(CE, 2, 1)
    PASS_G(CE, 4, 4)  PASS_G(CE, 4, 2)  PASS_G(CE, 4, 1)
    PASS_G(CE, 8, 8)  PASS_G(CE, 8, 4)  PASS_G(CE, 8, 2)  PASS_G(CE, 8, 1)
    PASS_G(CE_S, 16, 16) PASS_G(CE_S, 16, 8) PASS_G(CE_S, 16, 4)
    PASS_G(CE_S, 16, 2)  PASS_G(CE_S, 16, 1)
    PASS_G(CE_S, 32, 32) PASS_G(CE_S, 32, 16) PASS_G(CE_S, 32, 8)
    PASS_G(CE_S, 32, 4)  PASS_G(CE_S, 32, 2)  PASS_G(CE_S, 32, 1)

#undef PASS_G
#undef CE_S
#undef CE

    // ---- tie detection: adjacent keys sharing top-26 bits ----
    unsigned t0 = 0xFFFFFFFFu, t1 = 0xFFFFFFFFu, t2 = 0xFFFFFFFFu, t3 = 0xFFFFFFFFu;
    #pragma unroll
    for (int k2 = 0; k2 + 4 <= DD - 1; k2 += 4) {
        t0 = umin(t0, __float_as_uint(key[k2])     ^ __float_as_uint(key[k2 + 1]));
        t1 = umin(t1, __float_as_uint(key[k2 + 1]) ^ __float_as_uint(key[k2 + 2]));
        t2 = umin(t2, __float_as_uint(key[k2 + 2]) ^ __float_as_uint(key[k2 + 3]));
        t3 = umin(t3, __float_as_uint(key[k2 + 3]) ^ __float_as_uint(key[k2 + 4]));
    }
    t0 = umin(t0, __float_as_uint(key[52]) ^ __float_as_uint(key[53]));
    const unsigned tmin = umin(umin(t0, t1), umin(t2, t3));
    const bool slow = __any_sync(0xFFFFFFFFu, tmin < 64u) | tinyw;

    float y;
    if (!slow) {
        // ---- fast path (exact) ----
        float acc = 0.0f;
        unsigned selk = __float_as_uint(key[0]);
        #pragma unroll
        for (int k2 = 0; k2 < DD; k2++) {
            const unsigned ck = __float_as_uint(key[k2]);
            acc += wrow[ck & 63u];
            if (acc <= bs) selk = ck;
        }
        const int d = 63 - (int)(selk & 63u);
        const float t = tile_s[toff_s[d] + ty];
        const float m = mflat[(d < 27) ? (2 * d) : (2 * d - 53)];
        y = (d < 27) ? (t + m) : (m - t);
    } else {
        // ---- repair path: full-precision adjacent-tie repair + nz checks ----
        float acc = 0.0f, ans = 0.0f;
        bool seen = false;

        unsigned pk = __float_as_uint(key[0]);
        int dp = 63 - (int)(pk & 63u);
        float tp = tile_s[toff_s[dp] + ty];
        float mp = mflat[(dp < 27) ? (2 * dp) : (2 * dp - 53)];
        float pv = (dp < 27) ? (tp + mp) : (mp - tp);
        float pw = wrow[pk & 63u];

        #pragma unroll
        for (int k2 = 1; k2 < DD; k2++) {
            const unsigned ck = __float_as_uint(key[k2]);
            const unsigned sl = ck & 63u;
            const int dc = 63 - (int)sl;
            const float tc = tile_s[toff_s[dc] + ty];
            const float mc = mflat[(dc < 27) ? (2 * dc) : (2 * dc - 53)];
            const float cv = (dc < 27) ? (tc + mc) : (mc - tc);
            const float cw = wrow[sl];

            const bool sw = ((pk ^ ck) < 64u) && (cv > pv);
            const float ev = sw ? cv : pv;
            const float ew = sw ? cw : pw;
            pv = sw ? pv : cv;
            pw = sw ? pw : cw;
            pk = ck;

            const bool nz = ew > ZTOL;
            if (nz) acc += ew;
            if (nz && ((acc <= bs) || !seen)) ans = ev;
            seen |= nz;
        }
        {
            const bool nz = pw > ZTOL;
            if (nz) acc += pw;
            if (nz && ((acc <= bs) || !seen)) ans = pv;
        }
        y = ans;
    }

    // raw .view(B, NC, H, W): channel fastest -> coalesced
    const int l = h * WW + (w0 + ty);
    out[b * (NCH * HH * WW) + l * NCH + c] = y;
}

extern "C" void kernel_launch(void* const* d_in, const int* in_sizes, int n_in,
                              void* d_out, int out_size)
{
    const float* x      = (const float*)d_in[0];
    const float* mask   = (const float*)d_in[1];
    const float* weight = (const float*)d_in[2];
    const float* bias   = (const float*)d_in[3];
    float* out = (float*)d_out;

    const int B = in_sizes[0] / (3 * HH * WW);
    const int npix = B * HH * WW;
    dim3 grid(npix / PIX_PER_BLK);
    wos_kernel<<<grid, NTHREADS>>>(x, mask, weight, bias, out);
}